// round 11
// baseline (speedup 1.0000x reference)
#include <cuda_runtime.h>

// MKMMD loss, B=256, D=256, n=512, KERNEL_MUL=2, KERNEL_NUM=5, FIX_SIGMA=None.
// SINGLE fused kernel, 128 blocks x 256 threads. The input is read ONCE:
// stats are computed from the loss pairs' already-loaded pa-rows (grp0 pa
// covers all src rows, grp1 pa covers all tgt rows), staged via smem.
// Barrier machinery is the R10-proven pattern (fence-before-counter,
// per-block volatile poll slots), with the 256-fences-per-block storm
// reduced to ONE tid0 fence (PTX fence cumulativity through syncthreads).
//
// Math:
//  - sum(l2_cum) over (n,n,D) = sum_f (D-f) * (2n*S2_f - 2*S1_f^2)
//  - only 4B=1024 (row,row) pairs contribute
//  - exp(-x/(bw_base*2^k)) = e4^(2^(4-k)), e4 = exp(-x/(16*bw_base))
//  - inv16 = (n*n-n)/(4*bwsum) = 65408/bwsum
//  - cross-block loss accumulation in DOUBLE (float loses ~3e-3: R4)

#define BB 256
#define DD 256

#define NB  128
#define NT  256
#define NW  8
#define NSTATS 64                       // blocks 0..63 (grp0+grp1) do stats
#define PAD 32                          // one 128B line per slot

__device__ float        g_s1p[DD * PAD];
__device__ float        g_ws2f;
__device__ float        g_bw[NB * PAD]; // per-block inv16 slots (0 = not ready)
__device__ double       g_acc;
__device__ unsigned int g_done1;
__device__ unsigned int g_done2;

__global__ void __launch_bounds__(NT, 1) mkmmd_fused(
    const float* __restrict__ src, const float* __restrict__ tgt,
    float* __restrict__ out) {
    const int tid  = threadIdx.x;
    const int warp = tid >> 5;
    const int lane = tid & 31;
    const int bid  = blockIdx.x;

    __shared__ float s_rows[8 * DD];    // 8 pa-rows staged for column stats
    __shared__ float sh_red[NW];
    __shared__ float sh_inv;
    __shared__ bool  sh_last;

    // ---------------- pair setup + loads (the ONLY input reads) -------------
    const int p   = bid * NW + warp;            // 0..1023; grp uniform per blk
    const int grp = p >> 8;
    const int i   = p & (BB - 1);
    const int j   = (i + 1) & (BB - 1);

    const float* pa;
    const float* pb;
    float sign;
    if (grp == 0)      { pa = src + i * DD; pb = src + j * DD; sign =  1.f; }
    else if (grp == 1) { pa = tgt + i * DD; pb = tgt + j * DD; sign =  1.f; }
    else if (grp == 2) { pa = src + i * DD; pb = tgt + j * DD; sign = -1.f; }
    else               { pa = src + j * DD; pb = tgt + i * DD; sign = -1.f; }

    const float4* a4 = reinterpret_cast<const float4*>(pa) + lane * 2;
    const float4* b4 = reinterpret_cast<const float4*>(pb) + lane * 2;
    float4 a0 = a4[0], a1 = a4[1];
    float4 b0 = b4[0], b1 = b4[1];

    // ---------------- stats from pa-rows (grp0: src rows, grp1: tgt rows) ---
    if (bid < NSTATS) {
        // stage this warp's pa row: warp w holds row index (bid*8+w) of its
        // domain; smem layout s_rows[w*DD + feature]
        float4* sr4 = reinterpret_cast<float4*>(&s_rows[warp * DD]) + lane * 2;
        sr4[0] = a0;
        sr4[1] = a1;
        __syncthreads();

        // thread t owns column t: sum 8 staged rows (bank-conflict-free)
        float s1 = 0.f, s2 = 0.f;
#pragma unroll
        for (int r = 0; r < 8; ++r) {
            float v = s_rows[r * DD + tid];
            s1 += v;
            s2 = fmaf(v, v, s2);
        }
        atomicAdd(&g_s1p[tid * PAD], s1);           // RED (no return)

        float term = (float)(DD - tid) * s2;
#pragma unroll
        for (int off = 16; off > 0; off >>= 1)
            term += __shfl_xor_sync(0xffffffffu, term, off);
        if (lane == 0) sh_red[warp] = term;
        __syncthreads();        // release: all column REDs happen-before here

        if (tid == 0) {
            float bsum = 0.f;
#pragma unroll
            for (int w = 0; w < NW; ++w) bsum += sh_red[w];
            atomicAdd(&g_ws2f, bsum);
            __threadfence();    // cumulative: orders ALL block's REDs + ws2
            unsigned int c = atomicAdd(&g_done1, 1u);
            sh_last = (c == (unsigned int)(NSTATS - 1));
        }
        __syncthreads();

        // ---------------- publisher: bandwidth -> per-block slots -----------
        if (sh_last) {
            __threadfence();            // acquire: see all payload atomics
            float s  = __ldcg(&g_s1p[tid * PAD]);
            float tm = (float)(DD - tid) * s * s;
#pragma unroll
            for (int off = 16; off > 0; off >>= 1)
                tm += __shfl_xor_sync(0xffffffffu, tm, off);
            if (lane == 0) sh_red[warp] = tm;
            __syncthreads();
            if (tid == 0) {
                float s1sq = 0.f;
#pragma unroll
                for (int w = 0; w < NW; ++w) s1sq += sh_red[w];
                float ws2   = atomicAdd(&g_ws2f, 0.f);
                float bwsum = 1024.f * ws2 - 2.f * s1sq;  // 2n*ws2 - 2*s1sq
                sh_inv = 65408.f / bwsum;                 // (n^2-n)/(4*bwsum)
            }
            __syncthreads();
            if (tid < NB)
                *((volatile float*)&g_bw[tid * PAD]) = sh_inv;
        }
    }

    // ---------------- diffs + prefix scan (independent of bandwidth) --------
    float sq[8];
    {
        float d0 = a0.x - b0.x, d1 = a0.y - b0.y, d2 = a0.z - b0.z, d3 = a0.w - b0.w;
        float d4 = a1.x - b1.x, d5 = a1.y - b1.y, d6 = a1.z - b1.z, d7 = a1.w - b1.w;
        sq[0] = d0 * d0; sq[1] = d1 * d1; sq[2] = d2 * d2; sq[3] = d3 * d3;
        sq[4] = d4 * d4; sq[5] = d5 * d5; sq[6] = d6 * d6; sq[7] = d7 * d7;
    }
    float run = 0.f;
#pragma unroll
    for (int k = 0; k < 8; ++k) { run += sq[k]; sq[k] = run; }

    float pref = run;
#pragma unroll
    for (int off = 1; off < 32; off <<= 1) {
        float y = __shfl_up_sync(0xffffffffu, pref, off);
        if (lane >= off) pref += y;
    }
    const float excl = pref - run;

    // ---------------- poll own slot (value IS the payload) ------------------
    float inv16;
    {
        volatile float* slot = (volatile float*)&g_bw[bid * PAD];
        while ((inv16 = *slot) == 0.f) { }
    }

    // ---------------- Gaussian multi-kernel sum -----------------------------
    float lacc = 0.f;
#pragma unroll
    for (int k = 0; k < 8; ++k) {
        float y  = (sq[k] + excl) * inv16;
        float e4 = __expf(-y);
        float s  = e4;
        float t2 = e4 * e4;  s += t2;
        t2 *= t2;            s += t2;
        t2 *= t2;            s += t2;
        t2 *= t2;            s += t2;
        lacc += s;
    }
    lacc *= sign;

#pragma unroll
    for (int off = 16; off > 0; off >>= 1)
        lacc += __shfl_xor_sync(0xffffffffu, lacc, off);

    if (lane == 0) sh_red[warp] = lacc;
    __syncthreads();

    // ---------------- fenced tail: double atomic + counter ------------------
    if (tid == 0) {
        float bsum = 0.f;
#pragma unroll
        for (int w = 0; w < NW; ++w) bsum += sh_red[w];
        atomicAdd(&g_acc, (double)bsum);
        __threadfence();                // payload performed before counter
        unsigned int c = atomicAdd(&g_done2, 1u);
        sh_last = (c == (unsigned int)(NB - 1));
    }
    __syncthreads();

    // ---------------- final block: output + full state reset ----------------
    if (sh_last) {
        if (tid == 0) {
            __threadfence();            // acquire
            double tot = atomicAdd(&g_acc, 0.0);
            out[0] = (float)(tot * (1.0 / 65536.0));   // / (B*D)
            g_acc   = 0.0;
            g_ws2f  = 0.f;
            g_done1 = 0u;
            g_done2 = 0u;
        }
        g_s1p[tid * PAD] = 0.f;                        // reset for replay
        if (tid < NB) g_bw[tid * PAD] = 0.f;           // all polls already done
    }
}

extern "C" void kernel_launch(void* const* d_in, const int* in_sizes, int n_in,
                              void* d_out, int out_size) {
    const float* src = (const float*)d_in[0];
    const float* tgt = (const float*)d_in[1];
    float* out = (float*)d_out;
    (void)in_sizes; (void)n_in; (void)out_size;

    mkmmd_fused<<<NB, NT>>>(src, tgt, out);
}

// round 13
// speedup vs baseline: 1.7279x; 1.7279x over previous
#include <cuda_runtime.h>

// MKMMD loss, B=256, D=256, n=512, KERNEL_MUL=2, KERNEL_NUM=5, FIX_SIGMA=None.
// Two kernels; the kernel boundary is the grid barrier (measured cheaper than
// any in-kernel software barrier: fused=9.3us vs split sum=7.3us).
//
// K1 (stats, NO tail): load 4 rows/block, per-column REDs into padded slots,
//   one ws2 RED per block, exit. Kernel boundary publishes to K2.
// K2 (loss): each block computes inv16 in its prologue (256 L2 loads +
//   reduce, hidden under the pair rows' DRAM latency), then diffs, prefix
//   scan, 1 exp + 4 squarings, fenced DOUBLE atomic tail. The last arriver
//   RE-READS g_acc after the counter (R12's old+bsum shortcut was a race:
//   payload-before-own-counter does NOT make the last counter-arriver the
//   last payload-adder — rel_err 1309 measured). Final block resets state.
//
// Math:
//  - sum(l2_cum) over (n,n,D) = sum_f (D-f) * (2n*S2_f - 2*S1_f^2)
//  - only 4B=1024 (row,row) pairs contribute
//  - exp(-x/(bw_base*2^k)) = e4^(2^(4-k)), e4 = exp(-x/(16*bw_base))
//  - inv16 = (n*n-n)/(4*bwsum) = 65408/bwsum
//  - cross-block loss accumulation in DOUBLE (float loses ~3e-3: R4)

#define BB 256
#define DD 256

#define K1_BLOCKS 128
#define K1_THREADS 256
#define ROWS_PB 4

#define K2_BLOCKS 128
#define K2_THREADS 256
#define K2_WARPS 8

#define PAD 32                          // one 128B line per column slot

__device__ float        g_s1p[DD * PAD];
__device__ float        g_ws2f;
__device__ double       g_acc;
__device__ unsigned int g_done2;

// ---------------------------------------------------------------------------
// Kernel 1: stats only. 128 blocks x 256 threads, 4 rows each. No tail.
// ---------------------------------------------------------------------------
__global__ void __launch_bounds__(K1_THREADS, 1) stats_kernel(
    const float* __restrict__ src, const float* __restrict__ tgt) {
    const int t    = threadIdx.x;
    const int warp = t >> 5, lane = t & 31;
    const int r0   = blockIdx.x * ROWS_PB;

    float s1 = 0.f, s2 = 0.f;
#pragma unroll
    for (int k = 0; k < ROWS_PB; ++k) {
        int r = r0 + k;
        const float* row = (r < BB) ? (src + r * DD) : (tgt + (r - BB) * DD);
        float v = row[t];
        s1 += v;
        s2 = fmaf(v, v, s2);
    }
    atomicAdd(&g_s1p[t * PAD], s1);     // RED, no return needed

    float term = (float)(DD - t) * s2;
#pragma unroll
    for (int off = 16; off > 0; off >>= 1)
        term += __shfl_xor_sync(0xffffffffu, term, off);

    __shared__ float sh_red[K1_THREADS / 32];
    if (lane == 0) sh_red[warp] = term;
    __syncthreads();
    if (t == 0) {
        float bsum = 0.f;
#pragma unroll
        for (int w = 0; w < K1_THREADS / 32; ++w) bsum += sh_red[w];
        atomicAdd(&g_ws2f, bsum);       // RED
    }
    // exit; kernel boundary publishes everything to K2
}

// ---------------------------------------------------------------------------
// Kernel 2: per-block bandwidth (hidden under DRAM wait) + loss + tail.
// ---------------------------------------------------------------------------
__global__ void __launch_bounds__(K2_THREADS, 1) loss_kernel(
    const float* __restrict__ src, const float* __restrict__ tgt,
    float* __restrict__ out) {
    const int tid  = threadIdx.x;
    const int warp = tid >> 5;
    const int lane = tid & 31;

    __shared__ float sh_red[K2_WARPS];
    __shared__ float sh_inv;

    // ---- issue ALL loads up front: pair rows (DRAM) + column sums (L2) ----
    const int p   = blockIdx.x * K2_WARPS + warp;   // 0..1023; grp uniform/blk
    const int grp = p >> 8;
    const int i   = p & (BB - 1);
    const int j   = (i + 1) & (BB - 1);

    const float* pa;
    const float* pb;
    float sign;
    if (grp == 0)      { pa = src + i * DD; pb = src + j * DD; sign =  1.f; }
    else if (grp == 1) { pa = tgt + i * DD; pb = tgt + j * DD; sign =  1.f; }
    else if (grp == 2) { pa = src + i * DD; pb = tgt + j * DD; sign = -1.f; }
    else               { pa = src + j * DD; pb = tgt + i * DD; sign = -1.f; }

    const float4* a4 = reinterpret_cast<const float4*>(pa) + lane * 2;
    const float4* b4 = reinterpret_cast<const float4*>(pb) + lane * 2;
    float4 a0 = a4[0], a1 = a4[1];
    float4 b0 = b4[0], b1 = b4[1];
    float  sv  = g_s1p[tid * PAD];      // own column sum (L2)
    float  ws2 = g_ws2f;                // broadcast load (L2)

    // ---- per-block bandwidth finalize (overlaps the DRAM waits above) -----
    {
        float tm = (float)(DD - tid) * sv * sv;
#pragma unroll
        for (int off = 16; off > 0; off >>= 1)
            tm += __shfl_xor_sync(0xffffffffu, tm, off);
        if (lane == 0) sh_red[warp] = tm;
        __syncthreads();
        if (tid == 0) {
            float s1sq = 0.f;
#pragma unroll
            for (int w = 0; w < K2_WARPS; ++w) s1sq += sh_red[w];
            float bwsum = 1024.f * ws2 - 2.f * s1sq;   // 2n*ws2 - 2*s1sq
            sh_inv = 65408.f / bwsum;                  // (n^2-n)/(4*bwsum)
        }
        __syncthreads();
    }
    const float inv16 = sh_inv;

    // ---- squared diffs + in-lane prefix + warp exclusive scan ----
    float sq[8];
    {
        float d0 = a0.x - b0.x, d1 = a0.y - b0.y, d2 = a0.z - b0.z, d3 = a0.w - b0.w;
        float d4 = a1.x - b1.x, d5 = a1.y - b1.y, d6 = a1.z - b1.z, d7 = a1.w - b1.w;
        sq[0] = d0 * d0; sq[1] = d1 * d1; sq[2] = d2 * d2; sq[3] = d3 * d3;
        sq[4] = d4 * d4; sq[5] = d5 * d5; sq[6] = d6 * d6; sq[7] = d7 * d7;
    }
    float run = 0.f;
#pragma unroll
    for (int k = 0; k < 8; ++k) { run += sq[k]; sq[k] = run; }

    float pref = run;
#pragma unroll
    for (int off = 1; off < 32; off <<= 1) {
        float y = __shfl_up_sync(0xffffffffu, pref, off);
        if (lane >= off) pref += y;
    }
    const float excl = pref - run;

    // ---- Gaussian multi-kernel sum: 1 exp + 4 squarings ----
    float lacc = 0.f;
#pragma unroll
    for (int k = 0; k < 8; ++k) {
        float y  = (sq[k] + excl) * inv16;
        float e4 = __expf(-y);
        float s  = e4;
        float t2 = e4 * e4;  s += t2;
        t2 *= t2;            s += t2;
        t2 *= t2;            s += t2;
        t2 *= t2;            s += t2;
        lacc += s;
    }
    lacc *= sign;

#pragma unroll
    for (int off = 16; off > 0; off >>= 1)
        lacc += __shfl_xor_sync(0xffffffffu, lacc, off);

    if (lane == 0) sh_red[warp] = lacc;
    __syncthreads();

    // ---- tail: payload atomic -> fence -> counter; last arriver RE-READS --
    __shared__ bool sh_final;
    if (tid == 0) {
        float bsum = 0.f;
#pragma unroll
        for (int w = 0; w < K2_WARPS; ++w) bsum += sh_red[w];
        atomicAdd(&g_acc, (double)bsum);
        __threadfence();                // own payload performed before counter
        unsigned int c = atomicAdd(&g_done2, 1u);
        sh_final = (c == (unsigned int)(K2_BLOCKS - 1));
        if (sh_final) {
            // all 128 payloads are fenced-before their counters -> visible now
            double tot = atomicAdd(&g_acc, 0.0);
            out[0] = (float)(tot * (1.0 / 65536.0));   // / (B*D)
            g_acc   = 0.0;
            g_ws2f  = 0.f;
            g_done2 = 0u;
        }
    }
    __syncthreads();

    // ---- final block: reset column sums for the next graph replay ----
    if (sh_final) {
        g_s1p[tid * PAD] = 0.f;         // all reads of g_s1p happened long ago
    }
}

extern "C" void kernel_launch(void* const* d_in, const int* in_sizes, int n_in,
                              void* d_out, int out_size) {
    const float* src = (const float*)d_in[0];
    const float* tgt = (const float*)d_in[1];
    float* out = (float*)d_out;
    (void)in_sizes; (void)n_in; (void)out_size;

    stats_kernel<<<K1_BLOCKS, K1_THREADS>>>(src, tgt);
    loss_kernel<<<K2_BLOCKS, K2_THREADS>>>(src, tgt, out);
}